// round 1
// baseline (speedup 1.0000x reference)
#include <cuda_runtime.h>
#include <cstdint>

// FeatureResidual: 1-NN over 8-dim keys in a 100000x40 table, then feature residual.
// Shapes fixed by the problem instance.
#define BATCH  1024
#define KDIM   8
#define FDIM   32
#define NROWS  100000
#define NCOLS  40

#define NBLK   592                 // 4 blocks/SM * 148 SMs -> single wave
#define TPB    128
#define ROWS_PER ((NROWS + NBLK - 1) / NBLK)   // 169
#define TILE   256

typedef unsigned long long u64;

// Per-query packed (encoded_score << 32 | row). Min over this = max score, ties -> lowest row.
__device__ u64 g_best[BATCH];

// ---------- f32x2 helpers (Blackwell packed fp32) ----------
__device__ __forceinline__ u64 pack2(float lo, float hi) {
    u64 r; asm("mov.b64 %0, {%1, %2};" : "=l"(r) : "f"(lo), "f"(hi)); return r;
}
__device__ __forceinline__ void unpack2(u64 p, float &lo, float &hi) {
    asm("mov.b64 {%0, %1}, %2;" : "=f"(lo), "=f"(hi) : "l"(p));
}
__device__ __forceinline__ u64 fma2(u64 a, u64 b, u64 c) {
    u64 d; asm("fma.rn.f32x2 %0, %1, %2, %3;" : "=l"(d) : "l"(a), "l"(b), "l"(c)); return d;
}

// Monotonic-decreasing encode of float score (so u64-min == score-max).
__device__ __forceinline__ unsigned enc_max(float f) {
    unsigned b = __float_as_uint(f);
    b = (b & 0x80000000u) ? ~b : (b | 0x80000000u);  // monotonic increasing
    return ~b;                                        // flip -> monotonic decreasing
}

__global__ void init_kernel() {
    int t = blockIdx.x * blockDim.x + threadIdx.x;
    if (t < BATCH) g_best[t] = 0xFFFFFFFFFFFFFFFFULL;
}

__global__ __launch_bounds__(TPB, 4)
void argmin_kernel(const float* __restrict__ pk,
                   const float* __restrict__ table,
                   const int*   __restrict__ kidx) {
    __shared__ __align__(16) float sK[TILE * KDIM];   // staged keys
    __shared__ float sNH[TILE];                        // -0.5 * ||k||^2
    __shared__ int   sKidx[KDIM];

    const int t = threadIdx.x;
    if (t < KDIM) sKidx[t] = kidx[t];

    // Each thread owns 8 queries: t + 128*j (j=0..7), as 4 f32x2 pairs:
    // pair p = (query t+128*(2p), query t+128*(2p+1)).
    u64 q[4][KDIM];
    #pragma unroll
    for (int p = 0; p < 4; p++) {
        const float4* pa = (const float4*)(pk + (size_t)(t + 128 * (2 * p)) * KDIM);
        const float4* pb = (const float4*)(pk + (size_t)(t + 128 * (2 * p + 1)) * KDIM);
        float4 a0 = pa[0], a1 = pa[1];
        float4 b0 = pb[0], b1 = pb[1];
        float a[KDIM] = {a0.x, a0.y, a0.z, a0.w, a1.x, a1.y, a1.z, a1.w};
        float b[KDIM] = {b0.x, b0.y, b0.z, b0.w, b1.x, b1.y, b1.z, b1.w};
        #pragma unroll
        for (int i = 0; i < KDIM; i++) q[p][i] = pack2(a[i], b[i]);
    }

    float bs[8];   // best score (maximize)
    int   bi[8];
    #pragma unroll
    for (int j = 0; j < 8; j++) { bs[j] = -__int_as_float(0x7f800000); bi[j] = 0; }

    const int rowBase = blockIdx.x * ROWS_PER;
    const int rowEnd  = min(rowBase + ROWS_PER, NROWS);

    for (int tile0 = rowBase; tile0 < rowEnd; tile0 += TILE) {
        const int nr = min(TILE, rowEnd - tile0);
        __syncthreads();
        // Stage keys of nr rows (each row's 8 key floats = one 32B sector in gmem).
        for (int e = t; e < nr * KDIM; e += TPB) {
            int r = e >> 3, c = e & 7;
            sK[e] = table[(size_t)(tile0 + r) * NCOLS + sKidx[c]];
        }
        __syncthreads();
        // Precompute -0.5*||k||^2 per staged row.
        for (int r = t; r < nr; r += TPB) {
            float4 k0 = *(const float4*)(sK + r * KDIM);
            float4 k1 = *(const float4*)(sK + r * KDIM + 4);
            float s = k0.x * k0.x;
            s = fmaf(k0.y, k0.y, s); s = fmaf(k0.z, k0.z, s); s = fmaf(k0.w, k0.w, s);
            s = fmaf(k1.x, k1.x, s); s = fmaf(k1.y, k1.y, s); s = fmaf(k1.z, k1.z, s);
            s = fmaf(k1.w, k1.w, s);
            sNH[r] = -0.5f * s;
        }
        __syncthreads();

        for (int r = 0; r < nr; r++) {
            float4 k0 = *(const float4*)(sK + r * KDIM);      // broadcast LDS.128
            float4 k1 = *(const float4*)(sK + r * KDIM + 4);
            const float nh = sNH[r];
            u64 kp[KDIM];
            kp[0] = pack2(k0.x, k0.x); kp[1] = pack2(k0.y, k0.y);
            kp[2] = pack2(k0.z, k0.z); kp[3] = pack2(k0.w, k0.w);
            kp[4] = pack2(k1.x, k1.x); kp[5] = pack2(k1.y, k1.y);
            kp[6] = pack2(k1.z, k1.z); kp[7] = pack2(k1.w, k1.w);
            const u64 nh2 = pack2(nh, nh);
            const int row = tile0 + r;
            #pragma unroll
            for (int p = 0; p < 4; p++) {
                // score = q . k - 0.5*||k||^2  (argmax == argmin of squared dist)
                u64 acc = fma2(q[p][0], kp[0], nh2);
                #pragma unroll
                for (int i = 1; i < KDIM; i++) acc = fma2(q[p][i], kp[i], acc);
                float s0, s1; unpack2(acc, s0, s1);
                if (s0 > bs[2 * p])     { bs[2 * p]     = s0; bi[2 * p]     = row; }
                if (s1 > bs[2 * p + 1]) { bs[2 * p + 1] = s1; bi[2 * p + 1] = row; }
            }
        }
    }

    // Cross-block reduction: packed atomicMin. Equal scores -> lower row wins
    // (first-occurrence argmin, matching the reference).
    #pragma unroll
    for (int j = 0; j < 8; j++) {
        int qidx = t + 128 * j;
        u64 key = ((u64)enc_max(bs[j]) << 32) | (unsigned)bi[j];
        atomicMin(&g_best[qidx], key);
    }
}

__global__ void finalize_kernel(const float* __restrict__ feat,
                                const float* __restrict__ table,
                                const int*   __restrict__ fidx,
                                float* __restrict__ out) {
    int i = blockIdx.x * blockDim.x + threadIdx.x;
    if (i < BATCH * FDIM) {
        int b = i >> 5, f = i & 31;
        int row = (int)(unsigned)(g_best[b] & 0xFFFFFFFFULL);
        out[i] = feat[i] - table[(size_t)row * NCOLS + fidx[f]];
    }
}

extern "C" void kernel_launch(void* const* d_in, const int* in_sizes, int n_in,
                              void* d_out, int out_size) {
    const float* pk    = (const float*)d_in[0];  // predicted_key [1024,8]
    const float* feat  = (const float*)d_in[1];  // features      [1024,32]
    const float* table = (const float*)d_in[2];  // lookup_table  [100000,40]
    const int*   kidx  = (const int*)  d_in[3];  // lookup_key_indices [8]
    const int*   fidx  = (const int*)  d_in[4];  // feature_indices    [32]
    float* out = (float*)d_out;

    init_kernel<<<(BATCH + 255) / 256, 256>>>();
    argmin_kernel<<<NBLK, TPB>>>(pk, table, kidx);
    finalize_kernel<<<(BATCH * FDIM + 255) / 256, 256>>>(feat, table, fidx, out);
}

// round 2
// speedup vs baseline: 1.0406x; 1.0406x over previous
#include <cuda_runtime.h>
#include <cstdint>

// FeatureResidual: 1-NN over 8-dim keys in a 100000x40 table, then feature residual.
#define BATCH  1024
#define KDIM   8
#define FDIM   32
#define NROWS  100000
#define NCOLS  40

#define QGROUPS   2                 // query halves (512 queries each)
#define NSLICES   296               // row slices; grid = 296 x 2 = 592 blocks = 4/SM
#define TPB       128
#define QPT       4                 // queries per thread (128*4 = 512 per block)
#define ROWS_PER  ((NROWS + NSLICES - 1) / NSLICES)   // 338 (even)
#define MAXPAIRS  ((ROWS_PER + 1) / 2)                // 169

typedef unsigned long long u64;

// Per-query packed (enc(score) << 32 | ~row). Max = best score; ties -> lowest row.
// Zero-initialized at module load; finalize_kernel resets to 0 each call.
__device__ u64 g_best[BATCH];

// ---------- f32x2 helpers ----------
__device__ __forceinline__ u64 pack2(float lo, float hi) {
    u64 r; asm("mov.b64 %0, {%1, %2};" : "=l"(r) : "f"(lo), "f"(hi)); return r;
}
__device__ __forceinline__ void unpack2(u64 p, float &lo, float &hi) {
    asm("mov.b64 {%0, %1}, %2;" : "=f"(lo), "=f"(hi) : "l"(p));
}
__device__ __forceinline__ u64 fma2(u64 a, u64 b, u64 c) {
    u64 d; asm("fma.rn.f32x2 %0, %1, %2, %3;" : "=l"(d) : "l"(a), "l"(b), "l"(c)); return d;
}

// Monotonic-increasing encode of float (u32 compare order == float order).
__device__ __forceinline__ unsigned enc_inc(float f) {
    int s = __float_as_int(f);
    return (s < 0) ? ~(unsigned)s : ((unsigned)s | 0x80000000u);
}

__global__ __launch_bounds__(TPB, 4)
void argmin_kernel(const float* __restrict__ pk,
                   const float* __restrict__ table,
                   const int*   __restrict__ kidx) {
    // Row-pair interleaved keys: sK2[p*16 + 2*i + (r&1)] for row r=2p|2p+1, dim i.
    __shared__ __align__(16) float sK2[MAXPAIRS * 16];
    // -0.5*||k||^2, pair-adjacent so LDS.64 yields pack(nh0, nh1).
    __shared__ __align__(8) float sNH[MAXPAIRS * 2];
    __shared__ int sKidx[KDIM];

    const int t = threadIdx.x;
    if (t < KDIM) sKidx[t] = kidx[t];
    __syncthreads();

    const int rowBase = blockIdx.x * ROWS_PER;
    const int nr      = min(ROWS_PER, NROWS - rowBase);   // always even here
    const int npairs  = nr >> 1;

    // Stage keys (interleaved by row pair).
    for (int e = t; e < nr * KDIM; e += TPB) {
        int r = e >> 3, c = e & 7;
        float v = table[(size_t)(rowBase + r) * NCOLS + sKidx[c]];
        sK2[(r >> 1) * 16 + (c << 1) + (r & 1)] = v;
    }
    __syncthreads();
    // -0.5*||k||^2 per staged row.
    for (int r = t; r < nr; r += TPB) {
        const float* kr = sK2 + (r >> 1) * 16 + (r & 1);
        float s = kr[0] * kr[0];
        #pragma unroll
        for (int i = 1; i < KDIM; i++) s = fmaf(kr[2 * i], kr[2 * i], s);
        sNH[r] = -0.5f * s;
    }

    // Prologue: load 4 queries, duplicate-packed.
    const int qbase = blockIdx.y * (TPB * QPT);
    u64 q[QPT][KDIM];
    #pragma unroll
    for (int j = 0; j < QPT; j++) {
        const float4* pq = (const float4*)(pk + (size_t)(qbase + t + TPB * j) * KDIM);
        float4 a0 = pq[0], a1 = pq[1];
        float a[KDIM] = {a0.x, a0.y, a0.z, a0.w, a1.x, a1.y, a1.z, a1.w};
        #pragma unroll
        for (int i = 0; i < KDIM; i++) q[j][i] = pack2(a[i], a[i]);
    }

    float bs[QPT];
    int   bi[QPT];
    #pragma unroll
    for (int j = 0; j < QPT; j++) { bs[j] = -__int_as_float(0x7f800000); bi[j] = 0; }

    __syncthreads();

    for (int p = 0; p < npairs; p++) {
        const u64* kk  = (const u64*)(sK2 + p * 16);   // broadcast LDS.64 x8
        u64 k0 = kk[0], k1 = kk[1], k2 = kk[2], k3 = kk[3];
        u64 k4 = kk[4], k5 = kk[5], k6 = kk[6], k7 = kk[7];
        const u64 nh2 = *(const u64*)(sNH + p * 2);
        const int row0 = 2 * p;
        #pragma unroll
        for (int j = 0; j < QPT; j++) {
            // score = q.k - 0.5*||k||^2 for rows (2p, 2p+1) simultaneously
            u64 acc = fma2(q[j][0], k0, nh2);
            acc = fma2(q[j][1], k1, acc);
            acc = fma2(q[j][2], k2, acc);
            acc = fma2(q[j][3], k3, acc);
            acc = fma2(q[j][4], k4, acc);
            acc = fma2(q[j][5], k5, acc);
            acc = fma2(q[j][6], k6, acc);
            acc = fma2(q[j][7], k7, acc);
            float s0, s1; unpack2(acc, s0, s1);
            float m = fmaxf(s0, s1);
            if (m > bs[j]) {                      // strict: earlier pair wins ties
                bs[j] = m;
                bi[j] = row0 + (s1 > s0 ? 1 : 0); // strict: row0 wins in-pair ties
            }
        }
    }

    // Cross-block reduction: atomicMax of (enc(score)<<32 | ~row).
    // Larger enc wins; equal scores -> larger ~row = lower row (first occurrence).
    #pragma unroll
    for (int j = 0; j < QPT; j++) {
        int qidx = qbase + t + TPB * j;
        u64 key = ((u64)enc_inc(bs[j]) << 32) | (unsigned)(~(unsigned)(bi[j] + rowBase));
        atomicMax(&g_best[qidx], key);
    }
}

// One warp per query: lane0 reads winner, broadcasts, lanes compute residual,
// lane0 resets g_best for the next graph replay (deterministic).
__global__ void finalize_kernel(const float* __restrict__ feat,
                                const float* __restrict__ table,
                                const int*   __restrict__ fidx,
                                float* __restrict__ out) {
    int warp = (blockIdx.x * blockDim.x + threadIdx.x) >> 5;
    int lane = threadIdx.x & 31;
    if (warp >= BATCH) return;
    u64 v = 0;
    if (lane == 0) v = g_best[warp];
    v = __shfl_sync(0xFFFFFFFFu, v, 0);
    int row = (int)(~(unsigned)v);
    int col = fidx[lane];
    out[warp * FDIM + lane] = feat[warp * FDIM + lane]
                            - table[(size_t)row * NCOLS + col];
    if (lane == 0) g_best[warp] = 0ULL;
}

extern "C" void kernel_launch(void* const* d_in, const int* in_sizes, int n_in,
                              void* d_out, int out_size) {
    const float* pk    = (const float*)d_in[0];  // predicted_key [1024,8]
    const float* feat  = (const float*)d_in[1];  // features      [1024,32]
    const float* table = (const float*)d_in[2];  // lookup_table  [100000,40]
    const int*   kidx  = (const int*)  d_in[3];  // lookup_key_indices [8]
    const int*   fidx  = (const int*)  d_in[4];  // feature_indices    [32]
    float* out = (float*)d_out;

    dim3 grid(NSLICES, QGROUPS);
    argmin_kernel<<<grid, TPB>>>(pk, table, kidx);
    finalize_kernel<<<(BATCH * 32 + TPB - 1) / TPB, TPB>>>(feat, table, fidx, out);
}